// round 2
// baseline (speedup 1.0000x reference)
#include <cuda_runtime.h>
#include <cstdint>

// Problem constants: B=2, C=256, T=512, F=128, N=4 heads, H=CN=64, D=H*F=8192
#define TFsz 65536            // T*F
typedef unsigned long long u64;

// -------- scratch (device globals; no allocations allowed) --------
__device__ float g_Y3[100663296];   // [3][B][256][TF] pre/post-norm Q,K,V
__device__ float g_S[2097152];      // [8][512][512] attention scores / probs
__device__ float g_Z[33554432];     // [B][256][TF] permuted attention output
__device__ float g_Yp[33554432];    // [B][256][TF] final conv output (pre-norm)
__device__ float2 g_part[1536];     // partial (sum, sumsq)
__device__ float2 g_stats[32];      // (mu, rstd): [0..23] qkv groups, [24..25] final

// -------- packed fp32x2 helpers (FFMA2 path, sm_100+) --------
__device__ __forceinline__ u64 pk2(float lo, float hi) {
    u64 r; asm("mov.b64 %0, {%1, %2};" : "=l"(r) : "f"(lo), "f"(hi)); return r;
}
__device__ __forceinline__ void ffma2(u64& d, u64 a, u64 b) {
    asm("fma.rn.f32x2 %0, %1, %2, %0;" : "+l"(d) : "l"(a), "l"(b));
}
__device__ __forceinline__ float2 upk(u64 v) {
    float2 r; asm("mov.b64 {%0, %1}, %2;" : "=f"(r.x), "=f"(r.y) : "l"(v)); return r;
}

// Inner product step over one BK=8 smem tile pair. acc2[i][j] holds column
// pairs: j=0..1 -> cols tx*4+{0..3}, j=2..3 -> cols 64+tx*4+{0..3}.
__device__ __forceinline__ void mm_step(const float* As, const float* Bs,
                                        u64 acc2[8][4], int tx, int ty) {
#pragma unroll
    for (int k = 0; k < 8; k++) {
        const float* ar = As + k * 128;
        const float* br = Bs + k * 128;
        float4 a0 = *reinterpret_cast<const float4*>(ar + ty * 4);
        float4 a1 = *reinterpret_cast<const float4*>(ar + ty * 4 + 64);
        ulonglong2 b0 = *reinterpret_cast<const ulonglong2*>(br + tx * 4);
        ulonglong2 b1 = *reinterpret_cast<const ulonglong2*>(br + tx * 4 + 64);
        float av[8] = {a0.x, a0.y, a0.z, a0.w, a1.x, a1.y, a1.z, a1.w};
        u64 bv[4] = {b0.x, b0.y, b1.x, b1.y};
#pragma unroll
        for (int i = 0; i < 8; i++) {
            u64 ad = pk2(av[i], av[i]);
#pragma unroll
            for (int j = 0; j < 4; j++) ffma2(acc2[i][j], ad, bv[j]);
        }
    }
}

__device__ __forceinline__ void unpack_acc(u64 acc2[8][4], float acc[8][8]) {
#pragma unroll
    for (int i = 0; i < 8; i++)
#pragma unroll
        for (int j = 0; j < 4; j++) {
            float2 p = upk(acc2[i][j]);
            acc[i][2 * j] = p.x;
            acc[i][2 * j + 1] = p.y;
        }
}

// ---------------------------------------------------------------------------
// GEMM 1: 1x1 conv. Out[tens][b][o][j] = bias[o] + sum_c W[o][c] * X[b][c][j]
// grid (TF/128, 2*nTens, B), 256 threads. For proj pass same W thrice, grid.y=2.
// ---------------------------------------------------------------------------
__global__ void __launch_bounds__(256, 2) gemm_conv_kernel(
    const float* __restrict__ X, float* __restrict__ Out,
    const float* __restrict__ W0, const float* __restrict__ W1, const float* __restrict__ W2,
    const float* __restrict__ b0, const float* __restrict__ b1, const float* __restrict__ b2)
{
    __shared__ __align__(16) float As[8][128];
    __shared__ __align__(16) float Bs[8][128];
    const int bb = blockIdx.z;
    const int tens = blockIdx.y >> 1;
    const int o0 = (blockIdx.y & 1) * 128;
    const int j0 = blockIdx.x * 128;
    const float* W    = (tens == 0) ? W0 : (tens == 1) ? W1 : W2;
    const float* bias = (tens == 0) ? b0 : (tens == 1) ? b1 : b2;
    const float* Xb = X + (size_t)bb * (256 * (size_t)TFsz);
    float* O = Out + ((size_t)tens * 2 + bb) * (256 * (size_t)TFsz);

    const int tid = threadIdx.x;
    const int tx = tid & 15, ty = tid >> 4;
    const int arow = tid >> 1, ak = (tid & 1) * 4;
    const int brow = tid >> 5, bcol = (tid & 31) * 4;

    u64 acc2[8][4];
#pragma unroll
    for (int i = 0; i < 8; i++)
#pragma unroll
        for (int j = 0; j < 4; j++) acc2[i][j] = 0ull;

    for (int k0 = 0; k0 < 256; k0 += 8) {
        float4 a4 = *reinterpret_cast<const float4*>(&W[(size_t)(o0 + arow) * 256 + k0 + ak]);
        As[ak + 0][arow] = a4.x; As[ak + 1][arow] = a4.y;
        As[ak + 2][arow] = a4.z; As[ak + 3][arow] = a4.w;
        *reinterpret_cast<float4*>(&Bs[brow][bcol]) =
            *reinterpret_cast<const float4*>(&Xb[(size_t)(k0 + brow) * TFsz + j0 + bcol]);
        __syncthreads();
        mm_step(&As[0][0], &Bs[0][0], acc2, tx, ty);
        __syncthreads();
    }

    float acc[8][8];
    unpack_acc(acc2, acc);
#pragma unroll
    for (int ih = 0; ih < 2; ih++)
#pragma unroll
        for (int i2 = 0; i2 < 4; i2++) {
            int o = o0 + ih * 64 + ty * 4 + i2;
            float bv_ = bias[o];
#pragma unroll
            for (int jh = 0; jh < 2; jh++) {
                float4 v;
                v.x = acc[ih * 4 + i2][jh * 4 + 0] + bv_;
                v.y = acc[ih * 4 + i2][jh * 4 + 1] + bv_;
                v.z = acc[ih * 4 + i2][jh * 4 + 2] + bv_;
                v.w = acc[ih * 4 + i2][jh * 4 + 3] + bv_;
                *reinterpret_cast<float4*>(&O[(size_t)o * TFsz + j0 + jh * 64 + tx * 4]) = v;
            }
        }
}

// ---------------------------------------------------------------------------
// Stage-1 reduction: per-group (sum, sumsq) partials. Groups are contiguous.
// ---------------------------------------------------------------------------
__global__ void __launch_bounds__(256) reduce_part_kernel(
    const float* __restrict__ Y, float2* __restrict__ part, long long gsz, int bpg)
{
    const int g = blockIdx.y;
    const size_t chunk = (size_t)gsz / bpg;
    const float* p = Y + (size_t)g * (size_t)gsz + (size_t)blockIdx.x * chunk;
    float s = 0.f, s2 = 0.f;
    for (size_t i = (size_t)threadIdx.x * 4; i < chunk; i += 1024) {
        float4 v = *reinterpret_cast<const float4*>(&p[i]);
        s  += (v.x + v.y) + (v.z + v.w);
        s2 += (v.x * v.x + v.y * v.y) + (v.z * v.z + v.w * v.w);
    }
    __shared__ float sh[256], sh2[256];
    int t = threadIdx.x;
    sh[t] = s; sh2[t] = s2;
    __syncthreads();
    for (int off = 128; off > 0; off >>= 1) {
        if (t < off) { sh[t] += sh[t + off]; sh2[t] += sh2[t + off]; }
        __syncthreads();
    }
    if (t == 0) part[g * bpg + blockIdx.x] = make_float2(sh[0], sh2[0]);
}

__global__ void __launch_bounds__(256) reduce_final_kernel(
    const float2* __restrict__ part, float2* __restrict__ stats, int bpg, float inv_n)
{
    const int g = blockIdx.x;
    float s = 0.f, s2 = 0.f;
    for (int i = threadIdx.x; i < bpg; i += 256) {
        float2 v = part[g * bpg + i];
        s += v.x; s2 += v.y;
    }
    __shared__ float sh[256], sh2[256];
    int t = threadIdx.x;
    sh[t] = s; sh2[t] = s2;
    __syncthreads();
    for (int off = 128; off > 0; off >>= 1) {
        if (t < off) { sh[t] += sh[t + off]; sh2[t] += sh2[t + off]; }
        __syncthreads();
    }
    if (t == 0) {
        float mu = sh[0] * inv_n;
        float var = fmaxf(sh2[0] * inv_n - mu * mu, 0.f);
        stats[g] = make_float2(mu, rsqrtf(var + 1e-6f));
    }
}

// ---------------------------------------------------------------------------
// Apply GroupNorm affine + PReLU(0.25) in-place over all of Q,K,V.
// Layout [tens][b][o][tf]; group id = i >> 22 (blocks of 64 channels).
// ---------------------------------------------------------------------------
__global__ void __launch_bounds__(256) apply_qkv_kernel(
    const float* __restrict__ gq, const float* __restrict__ betaq,
    const float* __restrict__ gk, const float* __restrict__ betak,
    const float* __restrict__ gv, const float* __restrict__ betav)
{
    size_t i = ((size_t)blockIdx.x * 256 + threadIdx.x) * 4;
    int r = (int)(i >> 16);          // [tens*512 + b*256 + o]
    int o = r & 255;
    int tens = r >> 9;
    int g = (int)(i >> 22);
    float2 st = g_stats[g];
    const float* gw = (tens == 0) ? gq : (tens == 1) ? gk : gv;
    const float* bw = (tens == 0) ? betaq : (tens == 1) ? betak : betav;
    float gg = gw[o] * st.y;
    float ofs = bw[o] - st.x * gg;
    float4 v = *reinterpret_cast<const float4*>(&g_Y3[i]);
    v.x = fmaf(v.x, gg, ofs); v.x = (v.x >= 0.f) ? v.x : 0.25f * v.x;
    v.y = fmaf(v.y, gg, ofs); v.y = (v.y >= 0.f) ? v.y : 0.25f * v.y;
    v.z = fmaf(v.z, gg, ofs); v.z = (v.z >= 0.f) ? v.z : 0.25f * v.z;
    v.w = fmaf(v.w, gg, ofs); v.w = (v.w >= 0.f) ? v.w : 0.25f * v.w;
    *reinterpret_cast<float4*>(&g_Y3[i]) = v;
}

// ---------------------------------------------------------------------------
// GEMM 2 (NT): S[g][t][s] = scale * sum_{h,f} Q(t;h,f) K(s;h,f)
// Q element (h,t,f) at group base + h*65536 + t*128 + f. grid (4,4,8).
// ---------------------------------------------------------------------------
__global__ void __launch_bounds__(256, 2) gemm_qk_kernel()
{
    __shared__ __align__(16) float As[8][128];
    __shared__ __align__(16) float Bs[8][128];
    const int g = blockIdx.z;     // b*4 + n
    const float* Q  = g_Y3 + (size_t)g * 4194304;
    const float* Km = g_Y3 + 8ull * 4194304 + (size_t)g * 4194304;
    const int t0 = blockIdx.y * 128;
    const int s0 = blockIdx.x * 128;
    const int tid = threadIdx.x;
    const int tx = tid & 15, ty = tid >> 4;
    const int arow = tid >> 1, ak = (tid & 1) * 4;

    u64 acc2[8][4];
#pragma unroll
    for (int i = 0; i < 8; i++)
#pragma unroll
        for (int j = 0; j < 4; j++) acc2[i][j] = 0ull;

    for (int k0 = 0; k0 < 8192; k0 += 8) {
        const size_t hb = (size_t)(k0 >> 7) * 65536 + (size_t)(k0 & 127);
        float4 a4 = *reinterpret_cast<const float4*>(&Q[hb + (size_t)(t0 + arow) * 128 + ak]);
        As[ak + 0][arow] = a4.x; As[ak + 1][arow] = a4.y;
        As[ak + 2][arow] = a4.z; As[ak + 3][arow] = a4.w;
        float4 b4 = *reinterpret_cast<const float4*>(&Km[hb + (size_t)(s0 + arow) * 128 + ak]);
        Bs[ak + 0][arow] = b4.x; Bs[ak + 1][arow] = b4.y;
        Bs[ak + 2][arow] = b4.z; Bs[ak + 3][arow] = b4.w;
        __syncthreads();
        mm_step(&As[0][0], &Bs[0][0], acc2, tx, ty);
        __syncthreads();
    }

    const float scale = 0.011048543456039806f;   // 1/sqrt(8192)
    float acc[8][8];
    unpack_acc(acc2, acc);
    float* Sg = g_S + (size_t)g * 262144;
#pragma unroll
    for (int ih = 0; ih < 2; ih++)
#pragma unroll
        for (int i2 = 0; i2 < 4; i2++) {
            int t = t0 + ih * 64 + ty * 4 + i2;
#pragma unroll
            for (int jh = 0; jh < 2; jh++) {
                float4 v;
                v.x = acc[ih * 4 + i2][jh * 4 + 0] * scale;
                v.y = acc[ih * 4 + i2][jh * 4 + 1] * scale;
                v.z = acc[ih * 4 + i2][jh * 4 + 2] * scale;
                v.w = acc[ih * 4 + i2][jh * 4 + 3] * scale;
                *reinterpret_cast<float4*>(&Sg[(size_t)t * 512 + s0 + jh * 64 + tx * 4]) = v;
            }
        }
}

// ---------------------------------------------------------------------------
// Row softmax over 512 entries; one block per row (4096 rows).
// ---------------------------------------------------------------------------
__global__ void __launch_bounds__(256) softmax_kernel()
{
    float* p = g_S + (size_t)blockIdx.x * 512;
    const int t = threadIdx.x;
    float a = p[t], b = p[t + 256];
    __shared__ float sh[256];
    sh[t] = fmaxf(a, b);
    __syncthreads();
    for (int off = 128; off > 0; off >>= 1) {
        if (t < off) sh[t] = fmaxf(sh[t], sh[t + off]);
        __syncthreads();
    }
    float m = sh[0];
    __syncthreads();
    float e0 = __expf(a - m), e1 = __expf(b - m);
    sh[t] = e0 + e1;
    __syncthreads();
    for (int off = 128; off > 0; off >>= 1) {
        if (t < off) sh[t] += sh[t + off];
        __syncthreads();
    }
    float inv = 1.0f / sh[0];
    p[t] = e0 * inv;
    p[t + 256] = e1 * inv;
}

// ---------------------------------------------------------------------------
// GEMM 3 (NN): Vo = P @ V, written permuted: Z[b][n*64+cn][f*512 + t].
// grid (64 [cn d-tiles], 4 [t-tiles], 8 [groups]).
// ---------------------------------------------------------------------------
__global__ void __launch_bounds__(256, 2) gemm_pv_kernel()
{
    __shared__ __align__(16) float As[8][128];
    __shared__ __align__(16) float Bs[8][128];
    const int g = blockIdx.z;
    const int n = g & 3, bb = g >> 2;
    const float* P = g_S + (size_t)g * 262144;
    const int cn = blockIdx.x;     // d0 = cn*128, one cn per tile
    const float* Vb = g_Y3 + 16ull * 4194304 + (size_t)g * 4194304 + (size_t)cn * 65536;
    const int t0 = blockIdx.y * 128;
    float* Zb = g_Z + ((size_t)bb * 256 + (size_t)(n * 64 + cn)) * 65536;

    const int tid = threadIdx.x;
    const int tx = tid & 15, ty = tid >> 4;
    const int arow = tid >> 1, ak = (tid & 1) * 4;
    const int brow = tid >> 5, bcol = (tid & 31) * 4;

    u64 acc2[8][4];
#pragma unroll
    for (int i = 0; i < 8; i++)
#pragma unroll
        for (int j = 0; j < 4; j++) acc2[i][j] = 0ull;

    for (int k0 = 0; k0 < 512; k0 += 8) {
        float4 a4 = *reinterpret_cast<const float4*>(&P[(size_t)(t0 + arow) * 512 + k0 + ak]);
        As[ak + 0][arow] = a4.x; As[ak + 1][arow] = a4.y;
        As[ak + 2][arow] = a4.z; As[ak + 3][arow] = a4.w;
        *reinterpret_cast<float4*>(&Bs[brow][bcol]) =
            *reinterpret_cast<const float4*>(&Vb[(size_t)(k0 + brow) * 128 + bcol]);
        __syncthreads();
        mm_step(&As[0][0], &Bs[0][0], acc2, tx, ty);
        __syncthreads();
    }

    float acc[8][8];
    unpack_acc(acc2, acc);
    // Z[.][f*512 + t]: for fixed f, 4 consecutive t -> coalesced float4 stores
#pragma unroll
    for (int jh = 0; jh < 2; jh++)
#pragma unroll
        for (int jj = 0; jj < 4; jj++) {
            int f = jh * 64 + tx * 4 + jj;
            float* zp = Zb + (size_t)f * 512 + t0;
#pragma unroll
            for (int ih = 0; ih < 2; ih++) {
                float4 v = make_float4(acc[ih * 4 + 0][jh * 4 + jj],
                                       acc[ih * 4 + 1][jh * 4 + jj],
                                       acc[ih * 4 + 2][jh * 4 + jj],
                                       acc[ih * 4 + 3][jh * 4 + jj]);
                *reinterpret_cast<float4*>(&zp[ih * 64 + ty * 4]) = v;
            }
        }
}

// ---------------------------------------------------------------------------
// Final: out = PReLU(norm(Yp)*gp + betap) + x
// ---------------------------------------------------------------------------
__global__ void __launch_bounds__(256) apply_final_kernel(
    const float* __restrict__ x, const float* __restrict__ gp,
    const float* __restrict__ betap, const float2* __restrict__ stats2,
    float* __restrict__ out)
{
    size_t i = ((size_t)blockIdx.x * 256 + threadIdx.x) * 4;
    int r = (int)(i >> 16);      // b*256 + o
    int bidx = r >> 8;
    int o = r & 255;
    float2 st = stats2[bidx];
    float gg = gp[o] * st.y;
    float ofs = betap[o] - st.x * gg;
    float4 v  = *reinterpret_cast<const float4*>(&g_Yp[i]);
    float4 xr = *reinterpret_cast<const float4*>(&x[i]);
    v.x = fmaf(v.x, gg, ofs); v.x = ((v.x >= 0.f) ? v.x : 0.25f * v.x) + xr.x;
    v.y = fmaf(v.y, gg, ofs); v.y = ((v.y >= 0.f) ? v.y : 0.25f * v.y) + xr.y;
    v.z = fmaf(v.z, gg, ofs); v.z = ((v.z >= 0.f) ? v.z : 0.25f * v.z) + xr.z;
    v.w = fmaf(v.w, gg, ofs); v.w = ((v.w >= 0.f) ? v.w : 0.25f * v.w) + xr.w;
    *reinterpret_cast<float4*>(&out[i]) = v;
}

// ---------------------------------------------------------------------------
extern "C" void kernel_launch(void* const* d_in, const int* in_sizes, int n_in,
                              void* d_out, int out_size)
{
    const float* x     = (const float*)d_in[0];
    const float* Wq    = (const float*)d_in[1];
    const float* bq    = (const float*)d_in[2];
    const float* gq    = (const float*)d_in[3];
    const float* betaq = (const float*)d_in[4];
    const float* Wk    = (const float*)d_in[5];
    const float* bk    = (const float*)d_in[6];
    const float* gk    = (const float*)d_in[7];
    const float* betak = (const float*)d_in[8];
    const float* Wv    = (const float*)d_in[9];
    const float* bv    = (const float*)d_in[10];
    const float* gv    = (const float*)d_in[11];
    const float* betav = (const float*)d_in[12];
    const float* Wp    = (const float*)d_in[13];
    const float* bp    = (const float*)d_in[14];
    const float* gp    = (const float*)d_in[15];
    const float* betap = (const float*)d_in[16];

    float *Y3, *Z, *Yp;
    float2 *part, *stats;
    cudaGetSymbolAddress((void**)&Y3,   g_Y3);
    cudaGetSymbolAddress((void**)&Z,    g_Z);
    cudaGetSymbolAddress((void**)&Yp,   g_Yp);
    cudaGetSymbolAddress((void**)&part, g_part);
    cudaGetSymbolAddress((void**)&stats, g_stats);

    // 1) QKV projections (fused into one launch over 6 output row-tiles)
    gemm_conv_kernel<<<dim3(512, 6, 2), 256>>>(x, Y3, Wq, Wk, Wv, bq, bk, bv);
    // 2) GroupNorm stats: 24 groups of 4.19M contiguous elements
    reduce_part_kernel<<<dim3(64, 24), 256>>>(Y3, part, 4194304ll, 64);
    reduce_final_kernel<<<24, 256>>>(part, stats, 64, 1.0f / 4194304.0f);
    // 3) normalize + affine + PReLU in place
    apply_qkv_kernel<<<98304, 256>>>(gq, betaq, gk, betak, gv, betav);
    // 4) S = scale * Q K^T   (8 groups)
    gemm_qk_kernel<<<dim3(4, 4, 8), 256>>>();
    // 5) softmax rows
    softmax_kernel<<<4096, 256>>>();
    // 6) Vo = P V, permuted write into Z
    gemm_pv_kernel<<<dim3(64, 4, 8), 256>>>();
    // 7) final projection
    gemm_conv_kernel<<<dim3(512, 2, 2), 256>>>(Z, Yp, Wp, Wp, Wp, bp, bp, bp);
    // 8) final GroupNorm stats: 2 groups (per sample) of 16,777,216 elements
    reduce_part_kernel<<<dim3(128, 2), 256>>>(Yp, part, 16777216ll, 128);
    reduce_final_kernel<<<2, 256>>>(part, stats + 24, 128, 1.0f / 16777216.0f);
    // 9) normalize + PReLU + residual
    apply_final_kernel<<<32768, 256>>>(x, gp, betap, stats + 24, (float*)d_out);
}

// round 3
// speedup vs baseline: 1.1496x; 1.1496x over previous
#include <cuda_runtime.h>
#include <cstdint>

// Problem constants: B=2, C=256, T=512, F=128, N=4 heads, H=CN=64, D=H*F=8192
#define TFsz 65536            // T*F
typedef unsigned long long u64;

// -------- scratch (device globals; no allocations allowed) --------
__device__ float g_Y3[100663296];   // [3][B][256][TF] pre-norm Q,K,V
__device__ float g_Sp[8388608];     // [4 kchunks][8 g][512][512] partial scores
__device__ float g_S[2097152];      // [8][512][512] attention probs
__device__ float g_Z[33554432];     // [B][256][TF] permuted attention output
__device__ float g_Yp[33554432];    // [B][256][TF] final conv output (pre-norm)
__device__ float2 g_part[12288];    // partial (sum, sumsq) from GEMM epilogues
__device__ float2 g_stats[32];      // (mu, rstd): [0..23] qkv groups, [24..25] final

// -------- packed fp32x2 helpers (FFMA2 path, sm_100+) --------
__device__ __forceinline__ u64 pk2(float lo, float hi) {
    u64 r; asm("mov.b64 %0, {%1, %2};" : "=l"(r) : "f"(lo), "f"(hi)); return r;
}
__device__ __forceinline__ void ffma2(u64& d, u64 a, u64 b) {
    asm("fma.rn.f32x2 %0, %1, %2, %0;" : "+l"(d) : "l"(a), "l"(b));
}
__device__ __forceinline__ float2 upk(u64 v) {
    float2 r; asm("mov.b64 {%0, %1}, %2;" : "=f"(r.x), "=f"(r.y) : "l"(v)); return r;
}

// GroupNorm affine + PReLU(0.25) applied to one element
__device__ __forceinline__ float napply(float v, float gg, float of) {
    float y = fmaf(v, gg, of);
    return (y >= 0.f) ? y : 0.25f * y;
}

// Inner product step over one BK=8 smem tile pair. acc2[i][j] holds column
// pairs: j=0..1 -> cols tx*4+{0..3}, j=2..3 -> cols 64+tx*4+{0..3}.
__device__ __forceinline__ void mm_step(const float* As, const float* Bs,
                                        u64 acc2[8][4], int tx, int ty) {
#pragma unroll
    for (int k = 0; k < 8; k++) {
        const float* ar = As + k * 128;
        const float* br = Bs + k * 128;
        float4 a0 = *reinterpret_cast<const float4*>(ar + ty * 4);
        float4 a1 = *reinterpret_cast<const float4*>(ar + ty * 4 + 64);
        ulonglong2 b0 = *reinterpret_cast<const ulonglong2*>(br + tx * 4);
        ulonglong2 b1 = *reinterpret_cast<const ulonglong2*>(br + tx * 4 + 64);
        float av[8] = {a0.x, a0.y, a0.z, a0.w, a1.x, a1.y, a1.z, a1.w};
        u64 bv[4] = {b0.x, b0.y, b1.x, b1.y};
#pragma unroll
        for (int i = 0; i < 8; i++) {
            u64 ad = pk2(av[i], av[i]);
#pragma unroll
            for (int j = 0; j < 4; j++) ffma2(acc2[i][j], ad, bv[j]);
        }
    }
}

__device__ __forceinline__ void unpack_acc(u64 acc2[8][4], float acc[8][8]) {
#pragma unroll
    for (int i = 0; i < 8; i++)
#pragma unroll
        for (int j = 0; j < 4; j++) {
            float2 p = upk(acc2[i][j]);
            acc[i][2 * j] = p.x;
            acc[i][2 * j + 1] = p.y;
        }
}

// ---------------------------------------------------------------------------
// GEMM 1: 1x1 conv. Out[tens][b][o][j] = bias[o] + sum_c W[o][c] * X[b][c][j]
// grid (TF/128, 2*nTens, B), 256 threads. Epilogue also emits per-block
// (sum, sumsq) partials for the two 64-channel groups this tile covers:
//   part[((tens*2+b)*4 + (o>>6))*512 + jtile]
// ---------------------------------------------------------------------------
__global__ void __launch_bounds__(256, 2) gemm_conv_kernel(
    const float* __restrict__ X, float* __restrict__ Out,
    const float* __restrict__ W0, const float* __restrict__ W1, const float* __restrict__ W2,
    const float* __restrict__ b0, const float* __restrict__ b1, const float* __restrict__ b2,
    float2* __restrict__ part)
{
    __shared__ __align__(16) float As[8][128];
    __shared__ __align__(16) float Bs[8][128];
    const int bb = blockIdx.z;
    const int tens = blockIdx.y >> 1;
    const int o0 = (blockIdx.y & 1) * 128;
    const int j0 = blockIdx.x * 128;
    const float* W    = (tens == 0) ? W0 : (tens == 1) ? W1 : W2;
    const float* bias = (tens == 0) ? b0 : (tens == 1) ? b1 : b2;
    const float* Xb = X + (size_t)bb * (256 * (size_t)TFsz);
    float* O = Out + ((size_t)tens * 2 + bb) * (256 * (size_t)TFsz);

    const int tid = threadIdx.x;
    const int tx = tid & 15, ty = tid >> 4;
    const int arow = tid >> 1, ak = (tid & 1) * 4;
    const int brow = tid >> 5, bcol = (tid & 31) * 4;

    u64 acc2[8][4];
#pragma unroll
    for (int i = 0; i < 8; i++)
#pragma unroll
        for (int j = 0; j < 4; j++) acc2[i][j] = 0ull;

    for (int k0 = 0; k0 < 256; k0 += 8) {
        float4 a4 = *reinterpret_cast<const float4*>(&W[(size_t)(o0 + arow) * 256 + k0 + ak]);
        As[ak + 0][arow] = a4.x; As[ak + 1][arow] = a4.y;
        As[ak + 2][arow] = a4.z; As[ak + 3][arow] = a4.w;
        *reinterpret_cast<float4*>(&Bs[brow][bcol]) =
            *reinterpret_cast<const float4*>(&Xb[(size_t)(k0 + brow) * TFsz + j0 + bcol]);
        __syncthreads();
        mm_step(&As[0][0], &Bs[0][0], acc2, tx, ty);
        __syncthreads();
    }

    float acc[8][8];
    unpack_acc(acc2, acc);
    float ssum[2] = {0.f, 0.f}, ssq[2] = {0.f, 0.f};
#pragma unroll
    for (int ih = 0; ih < 2; ih++)
#pragma unroll
        for (int i2 = 0; i2 < 4; i2++) {
            int o = o0 + ih * 64 + ty * 4 + i2;
            float bv_ = bias[o];
#pragma unroll
            for (int jh = 0; jh < 2; jh++) {
                float4 v;
                v.x = acc[ih * 4 + i2][jh * 4 + 0] + bv_;
                v.y = acc[ih * 4 + i2][jh * 4 + 1] + bv_;
                v.z = acc[ih * 4 + i2][jh * 4 + 2] + bv_;
                v.w = acc[ih * 4 + i2][jh * 4 + 3] + bv_;
                ssum[ih] += (v.x + v.y) + (v.z + v.w);
                ssq[ih]  += (v.x * v.x + v.y * v.y) + (v.z * v.z + v.w * v.w);
                *reinterpret_cast<float4*>(&O[(size_t)o * TFsz + j0 + jh * 64 + tx * 4]) = v;
            }
        }

    // block-level reduction of partial stats (reuse smem tiles)
    float* sh  = &As[0][0];      // 512 floats used
    float* sh2 = &Bs[0][0];
    sh[tid] = ssum[0]; sh[256 + tid] = ssum[1];
    sh2[tid] = ssq[0]; sh2[256 + tid] = ssq[1];
    __syncthreads();
    for (int off = 128; off > 0; off >>= 1) {
        if (tid < off) {
            sh[tid] += sh[tid + off];   sh[256 + tid] += sh[256 + tid + off];
            sh2[tid] += sh2[tid + off]; sh2[256 + tid] += sh2[256 + tid + off];
        }
        __syncthreads();
    }
    if (tid < 2) {
        int og = (o0 >> 6) + tid;
        part[(((size_t)tens * 2 + bb) * 4 + og) * 512 + blockIdx.x] =
            make_float2(sh[tid * 256], sh2[tid * 256]);
    }
}

// ---------------------------------------------------------------------------
// Final reduction over `count` consecutive partials per group -> (mu, rstd)
// ---------------------------------------------------------------------------
__global__ void __launch_bounds__(256) reduce_final_kernel(
    const float2* __restrict__ part, float2* __restrict__ stats, int count, float inv_n)
{
    const int g = blockIdx.x;
    float s = 0.f, s2 = 0.f;
    for (int i = threadIdx.x; i < count; i += 256) {
        float2 v = part[(size_t)g * count + i];
        s += v.x; s2 += v.y;
    }
    __shared__ float sh[256], sh2[256];
    int t = threadIdx.x;
    sh[t] = s; sh2[t] = s2;
    __syncthreads();
    for (int off = 128; off > 0; off >>= 1) {
        if (t < off) { sh[t] += sh[t + off]; sh2[t] += sh2[t + off]; }
        __syncthreads();
    }
    if (t == 0) {
        float mu = sh[0] * inv_n;
        float var = fmaxf(sh2[0] * inv_n - mu * mu, 0.f);
        stats[g] = make_float2(mu, rsqrtf(var + 1e-6f));
    }
}

// ---------------------------------------------------------------------------
// GEMM 2 (NT, split-K x4): Sp[c][g][t][s] = scale * sum_{k in chunk} Q'(t,k) K'(s,k)
// where Q',K' are normalized+PReLU'd on the fly during smem loads.
// grid (4 s-tiles, 4 t-tiles, 32 = g*4+c), 256 threads.
// ---------------------------------------------------------------------------
__global__ void __launch_bounds__(256, 2) gemm_qk_kernel(
    const float* __restrict__ gq, const float* __restrict__ betaq,
    const float* __restrict__ gk, const float* __restrict__ betak)
{
    __shared__ __align__(16) float As[8][128];
    __shared__ __align__(16) float Bs[8][128];
    __shared__ float sgg[2][64], sof[2][64];
    const int z = blockIdx.z;
    const int g = z >> 2;         // b*4 + n
    const int c = z & 3;          // k-chunk
    const int n = g & 3;
    const float* Q  = g_Y3 + (size_t)g * 4194304;
    const float* Km = g_Y3 + 8ull * 4194304 + (size_t)g * 4194304;
    const int t0 = blockIdx.y * 128;
    const int s0 = blockIdx.x * 128;
    const int tid = threadIdx.x;
    const int tx = tid & 15, ty = tid >> 4;
    const int arow = tid >> 1, ak = (tid & 1) * 4;

    // stage norm params: which=0 -> Q, which=1 -> K
    if (tid < 128) {
        int which = tid >> 6;
        int h = tid & 63;
        int o = n * 64 + h;
        float2 st = g_stats[which * 8 + g];
        const float* gw = which ? gk : gq;
        const float* bw = which ? betak : betaq;
        float gg = gw[o] * st.y;
        sgg[which][h] = gg;
        sof[which][h] = bw[o] - st.x * gg;
    }
    __syncthreads();

    u64 acc2[8][4];
#pragma unroll
    for (int i = 0; i < 8; i++)
#pragma unroll
        for (int j = 0; j < 4; j++) acc2[i][j] = 0ull;

    const int kbeg = c * 2048, kend = kbeg + 2048;
    for (int k0 = kbeg; k0 < kend; k0 += 8) {
        const int h = k0 >> 7;
        const size_t hb = (size_t)h * 65536 + (size_t)(k0 & 127);
        float ggq_ = sgg[0][h], ofq_ = sof[0][h];
        float ggk_ = sgg[1][h], ofk_ = sof[1][h];
        float4 a4 = *reinterpret_cast<const float4*>(&Q[hb + (size_t)(t0 + arow) * 128 + ak]);
        As[ak + 0][arow] = napply(a4.x, ggq_, ofq_);
        As[ak + 1][arow] = napply(a4.y, ggq_, ofq_);
        As[ak + 2][arow] = napply(a4.z, ggq_, ofq_);
        As[ak + 3][arow] = napply(a4.w, ggq_, ofq_);
        float4 b4 = *reinterpret_cast<const float4*>(&Km[hb + (size_t)(s0 + arow) * 128 + ak]);
        Bs[ak + 0][arow] = napply(b4.x, ggk_, ofk_);
        Bs[ak + 1][arow] = napply(b4.y, ggk_, ofk_);
        Bs[ak + 2][arow] = napply(b4.z, ggk_, ofk_);
        Bs[ak + 3][arow] = napply(b4.w, ggk_, ofk_);
        __syncthreads();
        mm_step(&As[0][0], &Bs[0][0], acc2, tx, ty);
        __syncthreads();
    }

    const float scale = 0.011048543456039806f;   // 1/sqrt(8192)
    float acc[8][8];
    unpack_acc(acc2, acc);
    float* Sg = g_Sp + (size_t)c * 2097152 + (size_t)g * 262144;
#pragma unroll
    for (int ih = 0; ih < 2; ih++)
#pragma unroll
        for (int i2 = 0; i2 < 4; i2++) {
            int t = t0 + ih * 64 + ty * 4 + i2;
#pragma unroll
            for (int jh = 0; jh < 2; jh++) {
                float4 v;
                v.x = acc[ih * 4 + i2][jh * 4 + 0] * scale;
                v.y = acc[ih * 4 + i2][jh * 4 + 1] * scale;
                v.z = acc[ih * 4 + i2][jh * 4 + 2] * scale;
                v.w = acc[ih * 4 + i2][jh * 4 + 3] * scale;
                *reinterpret_cast<float4*>(&Sg[(size_t)t * 512 + s0 + jh * 64 + tx * 4]) = v;
            }
        }
}

// ---------------------------------------------------------------------------
// Row softmax over 512 entries, fusing the split-K partial sum.
// One block per row (4096 rows = g*512 + t).
// ---------------------------------------------------------------------------
__global__ void __launch_bounds__(256) softmax_kernel()
{
    const size_t row = (size_t)blockIdx.x * 512;
    const int t = threadIdx.x;
    float a = 0.f, b = 0.f;
#pragma unroll
    for (int c = 0; c < 4; c++) {
        const float* p = g_Sp + (size_t)c * 2097152 + row;
        a += p[t]; b += p[t + 256];
    }
    __shared__ float sh[256];
    sh[t] = fmaxf(a, b);
    __syncthreads();
    for (int off = 128; off > 0; off >>= 1) {
        if (t < off) sh[t] = fmaxf(sh[t], sh[t + off]);
        __syncthreads();
    }
    float m = sh[0];
    __syncthreads();
    float e0 = __expf(a - m), e1 = __expf(b - m);
    sh[t] = e0 + e1;
    __syncthreads();
    for (int off = 128; off > 0; off >>= 1) {
        if (t < off) sh[t] += sh[t + off];
        __syncthreads();
    }
    float inv = 1.0f / sh[0];
    float* q = g_S + row;
    q[t] = e0 * inv;
    q[t + 256] = e1 * inv;
}

// ---------------------------------------------------------------------------
// GEMM 3 (NN): Vo = P @ V' (V normalized+PReLU'd on the fly), written
// permuted: Z[b][n*64+cn][f*512 + t]. grid (64 cn, 4 t-tiles, 8 groups).
// ---------------------------------------------------------------------------
__global__ void __launch_bounds__(256, 2) gemm_pv_kernel(
    const float* __restrict__ gv, const float* __restrict__ betav)
{
    __shared__ __align__(16) float As[8][128];
    __shared__ __align__(16) float Bs[8][128];
    const int g = blockIdx.z;
    const int n = g & 3, bb = g >> 2;
    const float* P = g_S + (size_t)g * 262144;
    const int cn = blockIdx.x;
    const float* Vb = g_Y3 + 16ull * 4194304 + (size_t)g * 4194304 + (size_t)cn * 65536;
    const int t0 = blockIdx.y * 128;
    float* Zb = g_Z + ((size_t)bb * 256 + (size_t)(n * 64 + cn)) * 65536;

    const int tid = threadIdx.x;
    const int tx = tid & 15, ty = tid >> 4;
    const int arow = tid >> 1, ak = (tid & 1) * 4;
    const int brow = tid >> 5, bcol = (tid & 31) * 4;

    // per-block scalar norm params for this V channel
    float2 stv = g_stats[16 + g];
    float ggv = gv[n * 64 + cn] * stv.y;
    float ofv = betav[n * 64 + cn] - stv.x * ggv;

    u64 acc2[8][4];
#pragma unroll
    for (int i = 0; i < 8; i++)
#pragma unroll
        for (int j = 0; j < 4; j++) acc2[i][j] = 0ull;

    for (int k0 = 0; k0 < 512; k0 += 8) {
        float4 a4 = *reinterpret_cast<const float4*>(&P[(size_t)(t0 + arow) * 512 + k0 + ak]);
        As[ak + 0][arow] = a4.x; As[ak + 1][arow] = a4.y;
        As[ak + 2][arow] = a4.z; As[ak + 3][arow] = a4.w;
        float4 b4 = *reinterpret_cast<const float4*>(&Vb[(size_t)(k0 + brow) * 128 + bcol]);
        Bs[brow][bcol + 0] = napply(b4.x, ggv, ofv);
        Bs[brow][bcol + 1] = napply(b4.y, ggv, ofv);
        Bs[brow][bcol + 2] = napply(b4.z, ggv, ofv);
        Bs[brow][bcol + 3] = napply(b4.w, ggv, ofv);
        __syncthreads();
        mm_step(&As[0][0], &Bs[0][0], acc2, tx, ty);
        __syncthreads();
    }

    float acc[8][8];
    unpack_acc(acc2, acc);
    // Z[.][f*512 + t]: for fixed f, 4 consecutive t -> coalesced float4 stores
#pragma unroll
    for (int jh = 0; jh < 2; jh++)
#pragma unroll
        for (int jj = 0; jj < 4; jj++) {
            int f = jh * 64 + tx * 4 + jj;
            float* zp = Zb + (size_t)f * 512 + t0;
#pragma unroll
            for (int ih = 0; ih < 2; ih++) {
                float4 v = make_float4(acc[ih * 4 + 0][jh * 4 + jj],
                                       acc[ih * 4 + 1][jh * 4 + jj],
                                       acc[ih * 4 + 2][jh * 4 + jj],
                                       acc[ih * 4 + 3][jh * 4 + jj]);
                *reinterpret_cast<float4*>(&zp[ih * 64 + ty * 4]) = v;
            }
        }
}

// ---------------------------------------------------------------------------
// Final: out = PReLU(norm(Yp)*gp + betap) + x
// ---------------------------------------------------------------------------
__global__ void __launch_bounds__(256) apply_final_kernel(
    const float* __restrict__ x, const float* __restrict__ gp,
    const float* __restrict__ betap, const float2* __restrict__ stats2,
    float* __restrict__ out)
{
    size_t i = ((size_t)blockIdx.x * 256 + threadIdx.x) * 4;
    int r = (int)(i >> 16);      // b*256 + o
    int bidx = r >> 8;
    int o = r & 255;
    float2 st = stats2[bidx];
    float gg = gp[o] * st.y;
    float ofs = betap[o] - st.x * gg;
    float4 v  = *reinterpret_cast<const float4*>(&g_Yp[i]);
    float4 xr = *reinterpret_cast<const float4*>(&x[i]);
    v.x = fmaf(v.x, gg, ofs); v.x = ((v.x >= 0.f) ? v.x : 0.25f * v.x) + xr.x;
    v.y = fmaf(v.y, gg, ofs); v.y = ((v.y >= 0.f) ? v.y : 0.25f * v.y) + xr.y;
    v.z = fmaf(v.z, gg, ofs); v.z = ((v.z >= 0.f) ? v.z : 0.25f * v.z) + xr.z;
    v.w = fmaf(v.w, gg, ofs); v.w = ((v.w >= 0.f) ? v.w : 0.25f * v.w) + xr.w;
    *reinterpret_cast<float4*>(&out[i]) = v;
}

// ---------------------------------------------------------------------------
extern "C" void kernel_launch(void* const* d_in, const int* in_sizes, int n_in,
                              void* d_out, int out_size)
{
    const float* x     = (const float*)d_in[0];
    const float* Wq    = (const float*)d_in[1];
    const float* bq    = (const float*)d_in[2];
    const float* gq    = (const float*)d_in[3];
    const float* betaq = (const float*)d_in[4];
    const float* Wk    = (const float*)d_in[5];
    const float* bk    = (const float*)d_in[6];
    const float* gk    = (const float*)d_in[7];
    const float* betak = (const float*)d_in[8];
    const float* Wv    = (const float*)d_in[9];
    const float* bv    = (const float*)d_in[10];
    const float* gv    = (const float*)d_in[11];
    const float* betav = (const float*)d_in[12];
    const float* Wp    = (const float*)d_in[13];
    const float* bp    = (const float*)d_in[14];
    const float* gp    = (const float*)d_in[15];
    const float* betap = (const float*)d_in[16];

    float *Y3, *Z, *Yp;
    float2 *part, *stats;
    cudaGetSymbolAddress((void**)&Y3,   g_Y3);
    cudaGetSymbolAddress((void**)&Z,    g_Z);
    cudaGetSymbolAddress((void**)&Yp,   g_Yp);
    cudaGetSymbolAddress((void**)&part, g_part);
    cudaGetSymbolAddress((void**)&stats, g_stats);

    // 1) QKV projections + fused per-block norm partials
    gemm_conv_kernel<<<dim3(512, 6, 2), 256>>>(x, Y3, Wq, Wk, Wv, bq, bk, bv, part);
    // 2) finalize QKV GroupNorm stats: 24 groups x 512 partials
    reduce_final_kernel<<<24, 256>>>(part, stats, 512, 1.0f / 4194304.0f);
    // 3) S partials = scale * Q'K'^T  (split-K x4, norm fused into loads)
    gemm_qk_kernel<<<dim3(4, 4, 32), 256>>>(gq, betaq, gk, betak);
    // 4) softmax rows (fuses split-K reduction)
    softmax_kernel<<<4096, 256>>>();
    // 5) Vo = P V' (norm fused into loads), permuted write into Z
    gemm_pv_kernel<<<dim3(64, 4, 8), 256>>>(gv, betav);
    // 6) final projection + fused norm partials
    gemm_conv_kernel<<<dim3(512, 2, 2), 256>>>(Z, Yp, Wp, Wp, Wp, bp, bp, bp, part);
    // 7) finalize per-sample stats: 2 groups x 2048 partials
    reduce_final_kernel<<<2, 256>>>(part, stats + 24, 2048, 1.0f / 16777216.0f);
    // 8) normalize + PReLU + residual
    apply_final_kernel<<<32768, 256>>>(x, gp, betap, stats + 24, (float*)d_out);
}

// round 5
// speedup vs baseline: 1.5732x; 1.3685x over previous
#include <cuda_runtime.h>
#include <cstdint>

// Problem constants: B=2, C=256, T=512, F=128, N=4 heads, H=CN=64, D=H*F=8192
#define TFsz 65536            // T*F
typedef unsigned long long u64;

// -------- scratch (device globals; no allocations allowed) --------
__device__ float g_Y3[100663296];   // [3][B][256][TF] Q,K,V (pre-norm)
__device__ float g_Sp[8388608];     // [4 kchunks][8 g][512][512] partial scores
__device__ float g_S[2097152];      // [8][512][512] attention probs
__device__ float g_Z[33554432];     // [B][256][TF] permuted attention output
__device__ float g_Yp[33554432];    // [B][256][TF] final conv output (pre-norm)
__device__ float2 g_part[12288];    // partial (sum, sumsq) from GEMM epilogues
__device__ float2 g_stats[32];      // (mu, rstd): [0..23] qkv groups, [24..25] final

// -------- tf32 helpers (portable mma.sync path; no "a"-gated features) ----
__device__ __forceinline__ uint32_t f2tf32(float v) {
    uint32_t r; asm("cvt.rna.tf32.f32 %0, %1;" : "=r"(r) : "f"(v)); return r;
}
__device__ __forceinline__ void mma_tf32(float c[4], const uint32_t a[4], const uint32_t b[2]) {
    asm volatile(
        "mma.sync.aligned.m16n8k8.row.col.f32.tf32.tf32.f32 "
        "{%0,%1,%2,%3}, {%4,%5,%6,%7}, {%8,%9}, {%0,%1,%2,%3};"
        : "+f"(c[0]), "+f"(c[1]), "+f"(c[2]), "+f"(c[3])
        : "r"(a[0]), "r"(a[1]), "r"(a[2]), "r"(a[3]), "r"(b[0]), "r"(b[1]));
}

// -------- packed fp32x2 helpers (FFMA2 path) --------
__device__ __forceinline__ u64 pk2(float lo, float hi) {
    u64 r; asm("mov.b64 %0, {%1, %2};" : "=l"(r) : "f"(lo), "f"(hi)); return r;
}
__device__ __forceinline__ void ffma2(u64& d, u64 a, u64 b) {
    asm("fma.rn.f32x2 %0, %1, %2, %0;" : "+l"(d) : "l"(a), "l"(b));
}
__device__ __forceinline__ float2 upk(u64 v) {
    float2 r; asm("mov.b64 {%0, %1}, %2;" : "=f"(r.x), "=f"(r.y) : "l"(v)); return r;
}
__device__ __forceinline__ float napply(float v, float gg, float of) {
    float y = fmaf(v, gg, of);
    return (y >= 0.f) ? y : 0.25f * y;
}

__device__ __forceinline__ void mm_step(const float* As, const float* Bs,
                                        u64 acc2[8][4], int tx, int ty) {
#pragma unroll
    for (int k = 0; k < 8; k++) {
        const float* ar = As + k * 128;
        const float* br = Bs + k * 128;
        float4 a0 = *reinterpret_cast<const float4*>(ar + ty * 4);
        float4 a1 = *reinterpret_cast<const float4*>(ar + ty * 4 + 64);
        ulonglong2 b0 = *reinterpret_cast<const ulonglong2*>(br + tx * 4);
        ulonglong2 b1 = *reinterpret_cast<const ulonglong2*>(br + tx * 4 + 64);
        float av[8] = {a0.x, a0.y, a0.z, a0.w, a1.x, a1.y, a1.z, a1.w};
        u64 bv[4] = {b0.x, b0.y, b1.x, b1.y};
#pragma unroll
        for (int i = 0; i < 8; i++) {
            u64 ad = pk2(av[i], av[i]);
#pragma unroll
            for (int j = 0; j < 4; j++) ffma2(acc2[i][j], ad, bv[j]);
        }
    }
}

__device__ __forceinline__ void unpack_acc(u64 acc2[8][4], float acc[8][8]) {
#pragma unroll
    for (int i = 0; i < 8; i++)
#pragma unroll
        for (int j = 0; j < 4; j++) {
            float2 p = upk(acc2[i][j]);
            acc[i][2 * j] = p.x;
            acc[i][2 * j + 1] = p.y;
        }
}

// ---------------------------------------------------------------------------
// tf32 mma.sync conv GEMM: Out[tens*2+b][o][j] = bias[o] + sum_c W[o][c]*X[b][c][j]
// Block tile 128(o) x 128(j), K-chunks of 32. 8 warps: warp (w>>2) -> 64-o half,
// (w&3) -> 32-j quarter; each warp = 4x4 grid of m16n8k8 mma.
// Fragment maps (m16n8k8.row.col, lane g=l>>2, t=l&3):
//   A: a0=(g,t) a1=(g+8,t) a2=(g,t+4) a3=(g+8,t+4)
//   B: b0=(k=t,n=g) b1=(k=t+4,n=g)
//   C: c0=(g,2t) c1=(g,2t+1) c2=(g+8,2t) c3=(g+8,2t+1)
// Epilogue fuses bias + per-64-channel-group (sum,sumsq) partials.
// ---------------------------------------------------------------------------
__global__ void __launch_bounds__(256, 2) conv_mma_kernel(
    const float* __restrict__ X, float* __restrict__ Out,
    const float* __restrict__ W0, const float* __restrict__ W1, const float* __restrict__ W2,
    const float* __restrict__ b0_, const float* __restrict__ b1_, const float* __restrict__ b2_,
    float2* __restrict__ part)
{
    __shared__ __align__(16) uint32_t Ws[128][36];   // [o][k] tf32, pitch 36
    __shared__ __align__(16) uint32_t Xs[32][136];   // [k][j] tf32, pitch 136

    const int bb = blockIdx.z;
    const int y = blockIdx.y;
    const int tens = y >> 1;
    const int o0 = (y & 1) * 128;
    const int j0 = blockIdx.x * 128;
    const float* W    = (tens == 0) ? W0 : (tens == 1) ? W1 : W2;
    const float* bias = (tens == 0) ? b0_ : (tens == 1) ? b1_ : b2_;
    const float* Xb = X + (size_t)bb * (256 * (size_t)TFsz);
    float* O = Out + ((size_t)tens * 2 + bb) * (256 * (size_t)TFsz);

    const int tid = threadIdx.x;
    const int w = tid >> 5, l = tid & 31;
    const int g = l >> 2, t = l & 3;
    const int orow = w >> 2;          // 0/1 -> 64-o half
    const int jcol = w & 3;           // 0..3 -> 32-j quarter

    float c[4][4][4];
#pragma unroll
    for (int mt = 0; mt < 4; mt++)
#pragma unroll
        for (int nt = 0; nt < 4; nt++)
#pragma unroll
            for (int i = 0; i < 4; i++) c[mt][nt][i] = 0.f;

    for (int kc = 0; kc < 8; kc++) {
        // global loads first (overlap latency with previous chunk's mma)
        float4 wv[4], xv[4];
#pragma unroll
        for (int it = 0; it < 4; it++) {
            int i4 = tid + it * 256;
            int row = i4 >> 3, col4 = i4 & 7;
            wv[it] = *reinterpret_cast<const float4*>(
                &W[(size_t)(o0 + row) * 256 + kc * 32 + col4 * 4]);
            int xr = i4 >> 5, xc4 = i4 & 31;
            xv[it] = *reinterpret_cast<const float4*>(
                &Xb[(size_t)(kc * 32 + xr) * TFsz + j0 + xc4 * 4]);
        }
        __syncthreads();   // prior chunk's smem reads done
#pragma unroll
        for (int it = 0; it < 4; it++) {
            int i4 = tid + it * 256;
            int row = i4 >> 3, col4 = i4 & 7;
            Ws[row][col4 * 4 + 0] = f2tf32(wv[it].x);
            Ws[row][col4 * 4 + 1] = f2tf32(wv[it].y);
            Ws[row][col4 * 4 + 2] = f2tf32(wv[it].z);
            Ws[row][col4 * 4 + 3] = f2tf32(wv[it].w);
            int xr = i4 >> 5, xc4 = i4 & 31;
            uint4 u;
            u.x = f2tf32(xv[it].x); u.y = f2tf32(xv[it].y);
            u.z = f2tf32(xv[it].z); u.w = f2tf32(xv[it].w);
            *reinterpret_cast<uint4*>(&Xs[xr][xc4 * 4]) = u;
        }
        __syncthreads();

#pragma unroll
        for (int ks = 0; ks < 4; ks++) {
            const int kk = ks * 8;
            uint32_t a[4][4], b[4][2];
#pragma unroll
            for (int mt = 0; mt < 4; mt++) {
                int ow = orow * 64 + mt * 16 + g;
                a[mt][0] = Ws[ow][kk + t];
                a[mt][1] = Ws[ow + 8][kk + t];
                a[mt][2] = Ws[ow][kk + t + 4];
                a[mt][3] = Ws[ow + 8][kk + t + 4];
            }
#pragma unroll
            for (int nt = 0; nt < 4; nt++) {
                int jw = jcol * 32 + nt * 8 + g;
                b[nt][0] = Xs[kk + t][jw];
                b[nt][1] = Xs[kk + t + 4][jw];
            }
#pragma unroll
            for (int mt = 0; mt < 4; mt++)
#pragma unroll
                for (int nt = 0; nt < 4; nt++)
                    mma_tf32(c[mt][nt], a[mt], b[nt]);
        }
    }

    // epilogue: bias + stores + per-thread stats (warp's o range = one group)
    float bl[4], bh[4];
#pragma unroll
    for (int mt = 0; mt < 4; mt++) {
        bl[mt] = __ldg(&bias[o0 + orow * 64 + mt * 16 + g]);
        bh[mt] = __ldg(&bias[o0 + orow * 64 + mt * 16 + g + 8]);
    }
    float s = 0.f, sq = 0.f;
#pragma unroll
    for (int mt = 0; mt < 4; mt++) {
        const int o_lo = o0 + orow * 64 + mt * 16 + g;
#pragma unroll
        for (int nt = 0; nt < 4; nt++) {
            const int jj = j0 + jcol * 32 + nt * 8 + 2 * t;
            float v0 = c[mt][nt][0] + bl[mt];
            float v1 = c[mt][nt][1] + bl[mt];
            float v2 = c[mt][nt][2] + bh[mt];
            float v3 = c[mt][nt][3] + bh[mt];
            *reinterpret_cast<float2*>(&O[(size_t)o_lo * TFsz + jj]) = make_float2(v0, v1);
            *reinterpret_cast<float2*>(&O[(size_t)(o_lo + 8) * TFsz + jj]) = make_float2(v2, v3);
            s  += (v0 + v1) + (v2 + v3);
            sq += (v0 * v0 + v1 * v1) + (v2 * v2 + v3 * v3);
        }
    }

    __syncthreads();   // done with Ws/Xs; reuse as reduce scratch
    float* redS = reinterpret_cast<float*>(&Ws[0][0]);
    float* redQ = redS + 256;
    redS[tid] = s; redQ[tid] = sq;
    __syncthreads();
    const int r = tid & 127;
    for (int off = 64; off > 0; off >>= 1) {
        if (r < off) { redS[tid] += redS[tid + off]; redQ[tid] += redQ[tid + off]; }
        __syncthreads();
    }
    if (r == 0) {
        int og = (y & 1) * 2 + (tid >> 7);
        part[(((size_t)tens * 2 + bb) * 4 + og) * 512 + blockIdx.x] =
            make_float2(redS[tid], redQ[tid]);
    }
}

// ---------------------------------------------------------------------------
// Final reduction over `count` consecutive partials per group -> (mu, rstd)
// ---------------------------------------------------------------------------
__global__ void __launch_bounds__(256) reduce_final_kernel(
    const float2* __restrict__ part, float2* __restrict__ stats, int count, float inv_n)
{
    const int g = blockIdx.x;
    float s = 0.f, s2 = 0.f;
    for (int i = threadIdx.x; i < count; i += 256) {
        float2 v = part[(size_t)g * count + i];
        s += v.x; s2 += v.y;
    }
    __shared__ float sh[256], sh2[256];
    int t = threadIdx.x;
    sh[t] = s; sh2[t] = s2;
    __syncthreads();
    for (int off = 128; off > 0; off >>= 1) {
        if (t < off) { sh[t] += sh[t + off]; sh2[t] += sh2[t + off]; }
        __syncthreads();
    }
    if (t == 0) {
        float mu = sh[0] * inv_n;
        float var = fmaxf(sh2[0] * inv_n - mu * mu, 0.f);
        stats[g] = make_float2(mu, rsqrtf(var + 1e-6f));
    }
}

// ---------------------------------------------------------------------------
// GEMM 2 (NT, split-K x4): Sp[c][g][t][s] = scale * sum_{k} Q'(t,k) K'(s,k)
// (norm+PReLU fused into smem loads). grid (4, 4, 32), 256 threads.
// ---------------------------------------------------------------------------
__global__ void __launch_bounds__(256, 2) gemm_qk_kernel(
    const float* __restrict__ gq, const float* __restrict__ betaq,
    const float* __restrict__ gk, const float* __restrict__ betak)
{
    __shared__ __align__(16) float As[8][128];
    __shared__ __align__(16) float Bs[8][128];
    __shared__ float sgg[2][64], sof[2][64];
    const int z = blockIdx.z;
    const int g = z >> 2;
    const int c = z & 3;
    const int n = g & 3;
    const float* Q  = g_Y3 + (size_t)g * 4194304;
    const float* Km = g_Y3 + 8ull * 4194304 + (size_t)g * 4194304;
    const int t0 = blockIdx.y * 128;
    const int s0 = blockIdx.x * 128;
    const int tid = threadIdx.x;
    const int tx = tid & 15, ty = tid >> 4;
    const int arow = tid >> 1, ak = (tid & 1) * 4;

    if (tid < 128) {
        int which = tid >> 6;
        int h = tid & 63;
        int o = n * 64 + h;
        float2 st = g_stats[which * 8 + g];
        const float* gw = which ? gk : gq;
        const float* bw = which ? betak : betaq;
        float gg = gw[o] * st.y;
        sgg[which][h] = gg;
        sof[which][h] = bw[o] - st.x * gg;
    }
    __syncthreads();

    u64 acc2[8][4];
#pragma unroll
    for (int i = 0; i < 8; i++)
#pragma unroll
        for (int j = 0; j < 4; j++) acc2[i][j] = 0ull;

    const int kbeg = c * 2048, kend = kbeg + 2048;
    for (int k0 = kbeg; k0 < kend; k0 += 8) {
        const int h = k0 >> 7;
        const size_t hb = (size_t)h * 65536 + (size_t)(k0 & 127);
        float ggq_ = sgg[0][h], ofq_ = sof[0][h];
        float ggk_ = sgg[1][h], ofk_ = sof[1][h];
        float4 a4 = *reinterpret_cast<const float4*>(&Q[hb + (size_t)(t0 + arow) * 128 + ak]);
        As[ak + 0][arow] = napply(a4.x, ggq_, ofq_);
        As[ak + 1][arow] = napply(a4.y, ggq_, ofq_);
        As[ak + 2][arow] = napply(a4.z, ggq_, ofq_);
        As[ak + 3][arow] = napply(a4.w, ggq_, ofq_);
        float4 b4 = *reinterpret_cast<const float4*>(&Km[hb + (size_t)(s0 + arow) * 128 + ak]);
        Bs[ak + 0][arow] = napply(b4.x, ggk_, ofk_);
        Bs[ak + 1][arow] = napply(b4.y, ggk_, ofk_);
        Bs[ak + 2][arow] = napply(b4.z, ggk_, ofk_);
        Bs[ak + 3][arow] = napply(b4.w, ggk_, ofk_);
        __syncthreads();
        mm_step(&As[0][0], &Bs[0][0], acc2, tx, ty);
        __syncthreads();
    }

    const float scale = 0.011048543456039806f;   // 1/sqrt(8192)
    float acc[8][8];
    unpack_acc(acc2, acc);
    float* Sg = g_Sp + (size_t)c * 2097152 + (size_t)g * 262144;
#pragma unroll
    for (int ih = 0; ih < 2; ih++)
#pragma unroll
        for (int i2 = 0; i2 < 4; i2++) {
            int t = t0 + ih * 64 + ty * 4 + i2;
#pragma unroll
            for (int jh = 0; jh < 2; jh++) {
                float4 v;
                v.x = acc[ih * 4 + i2][jh * 4 + 0] * scale;
                v.y = acc[ih * 4 + i2][jh * 4 + 1] * scale;
                v.z = acc[ih * 4 + i2][jh * 4 + 2] * scale;
                v.w = acc[ih * 4 + i2][jh * 4 + 3] * scale;
                *reinterpret_cast<float4*>(&Sg[(size_t)t * 512 + s0 + jh * 64 + tx * 4]) = v;
            }
        }
}

// ---------------------------------------------------------------------------
// Row softmax over 512, fusing the split-K partial sum. 4096 blocks.
// ---------------------------------------------------------------------------
__global__ void __launch_bounds__(256) softmax_kernel()
{
    const size_t row = (size_t)blockIdx.x * 512;
    const int t = threadIdx.x;
    float a = 0.f, b = 0.f;
#pragma unroll
    for (int c = 0; c < 4; c++) {
        const float* p = g_Sp + (size_t)c * 2097152 + row;
        a += p[t]; b += p[t + 256];
    }
    __shared__ float sh[256];
    sh[t] = fmaxf(a, b);
    __syncthreads();
    for (int off = 128; off > 0; off >>= 1) {
        if (t < off) sh[t] = fmaxf(sh[t], sh[t + off]);
        __syncthreads();
    }
    float m = sh[0];
    __syncthreads();
    float e0 = __expf(a - m), e1 = __expf(b - m);
    sh[t] = e0 + e1;
    __syncthreads();
    for (int off = 128; off > 0; off >>= 1) {
        if (t < off) sh[t] += sh[t + off];
        __syncthreads();
    }
    float inv = 1.0f / sh[0];
    float* q = g_S + row;
    q[t] = e0 * inv;
    q[t + 256] = e1 * inv;
}

// ---------------------------------------------------------------------------
// GEMM 3 (NN): Vo = P @ V' (norm fused), permuted write Z[b][n*64+cn][f*512+t].
// grid (64 cn, 4 t-tiles, 8 groups).
// ---------------------------------------------------------------------------
__global__ void __launch_bounds__(256, 2) gemm_pv_kernel(
    const float* __restrict__ gv, const float* __restrict__ betav)
{
    __shared__ __align__(16) float As[8][128];
    __shared__ __align__(16) float Bs[8][128];
    const int g = blockIdx.z;
    const int n = g & 3, bb = g >> 2;
    const float* P = g_S + (size_t)g * 262144;
    const int cn = blockIdx.x;
    const float* Vb = g_Y3 + 16ull * 4194304 + (size_t)g * 4194304 + (size_t)cn * 65536;
    const int t0 = blockIdx.y * 128;
    float* Zb = g_Z + ((size_t)bb * 256 + (size_t)(n * 64 + cn)) * 65536;

    const int tid = threadIdx.x;
    const int tx = tid & 15, ty = tid >> 4;
    const int arow = tid >> 1, ak = (tid & 1) * 4;
    const int brow = tid >> 5, bcol = (tid & 31) * 4;

    float2 stv = g_stats[16 + g];
    float ggv = gv[n * 64 + cn] * stv.y;
    float ofv = betav[n * 64 + cn] - stv.x * ggv;

    u64 acc2[8][4];
#pragma unroll
    for (int i = 0; i < 8; i++)
#pragma unroll
        for (int j = 0; j < 4; j++) acc2[i][j] = 0ull;

    for (int k0 = 0; k0 < 512; k0 += 8) {
        float4 a4 = *reinterpret_cast<const float4*>(&P[(size_t)(t0 + arow) * 512 + k0 + ak]);
        As[ak + 0][arow] = a4.x; As[ak + 1][arow] = a4.y;
        As[ak + 2][arow] = a4.z; As[ak + 3][arow] = a4.w;
        float4 b4 = *reinterpret_cast<const float4*>(&Vb[(size_t)(k0 + brow) * 128 + bcol]);
        Bs[brow][bcol + 0] = napply(b4.x, ggv, ofv);
        Bs[brow][bcol + 1] = napply(b4.y, ggv, ofv);
        Bs[brow][bcol + 2] = napply(b4.z, ggv, ofv);
        Bs[brow][bcol + 3] = napply(b4.w, ggv, ofv);
        __syncthreads();
        mm_step(&As[0][0], &Bs[0][0], acc2, tx, ty);
        __syncthreads();
    }

    float acc[8][8];
    unpack_acc(acc2, acc);
#pragma unroll
    for (int jh = 0; jh < 2; jh++)
#pragma unroll
        for (int jj = 0; jj < 4; jj++) {
            int f = jh * 64 + tx * 4 + jj;
            float* zp = Zb + (size_t)f * 512 + t0;
#pragma unroll
            for (int ih = 0; ih < 2; ih++) {
                float4 v = make_float4(acc[ih * 4 + 0][jh * 4 + jj],
                                       acc[ih * 4 + 1][jh * 4 + jj],
                                       acc[ih * 4 + 2][jh * 4 + jj],
                                       acc[ih * 4 + 3][jh * 4 + jj]);
                *reinterpret_cast<float4*>(&zp[ih * 64 + ty * 4]) = v;
            }
        }
}

// ---------------------------------------------------------------------------
// Final: out = PReLU(norm(Yp)*gp + betap) + x
// ---------------------------------------------------------------------------
__global__ void __launch_bounds__(256) apply_final_kernel(
    const float* __restrict__ x, const float* __restrict__ gp,
    const float* __restrict__ betap, const float2* __restrict__ stats2,
    float* __restrict__ out)
{
    size_t i = ((size_t)blockIdx.x * 256 + threadIdx.x) * 4;
    int r = (int)(i >> 16);
    int bidx = r >> 8;
    int o = r & 255;
    float2 st = stats2[bidx];
    float gg = gp[o] * st.y;
    float ofs = betap[o] - st.x * gg;
    float4 v  = *reinterpret_cast<const float4*>(&g_Yp[i]);
    float4 xr = *reinterpret_cast<const float4*>(&x[i]);
    v.x = fmaf(v.x, gg, ofs); v.x = ((v.x >= 0.f) ? v.x : 0.25f * v.x) + xr.x;
    v.y = fmaf(v.y, gg, ofs); v.y = ((v.y >= 0.f) ? v.y : 0.25f * v.y) + xr.y;
    v.z = fmaf(v.z, gg, ofs); v.z = ((v.z >= 0.f) ? v.z : 0.25f * v.z) + xr.z;
    v.w = fmaf(v.w, gg, ofs); v.w = ((v.w >= 0.f) ? v.w : 0.25f * v.w) + xr.w;
    *reinterpret_cast<float4*>(&out[i]) = v;
}

// ---------------------------------------------------------------------------
extern "C" void kernel_launch(void* const* d_in, const int* in_sizes, int n_in,
                              void* d_out, int out_size)
{
    const float* x     = (const float*)d_in[0];
    const float* Wq    = (const float*)d_in[1];
    const float* bq    = (const float*)d_in[2];
    const float* gq    = (const float*)d_in[3];
    const float* betaq = (const float*)d_in[4];
    const float* Wk    = (const float*)d_in[5];
    const float* bk    = (const float*)d_in[6];
    const float* gk    = (const float*)d_in[7];
    const float* betak = (const float*)d_in[8];
    const float* Wv    = (const float*)d_in[9];
    const float* bv    = (const float*)d_in[10];
    const float* gv    = (const float*)d_in[11];
    const float* betav = (const float*)d_in[12];
    const float* Wp    = (const float*)d_in[13];
    const float* bp    = (const float*)d_in[14];
    const float* gp    = (const float*)d_in[15];
    const float* betap = (const float*)d_in[16];

    float *Y3, *Z, *Yp;
    float2 *part, *stats;
    cudaGetSymbolAddress((void**)&Y3,   g_Y3);
    cudaGetSymbolAddress((void**)&Z,    g_Z);
    cudaGetSymbolAddress((void**)&Yp,   g_Yp);
    cudaGetSymbolAddress((void**)&part, g_part);
    cudaGetSymbolAddress((void**)&stats, g_stats);

    // 1) QKV projections via tf32 mma.sync (+ fused norm partials)
    conv_mma_kernel<<<dim3(512, 6, 2), 256>>>(x, Y3, Wq, Wk, Wv, bq, bk, bv, part);
    // 2) finalize QKV GroupNorm stats: 24 groups x 512 partials
    reduce_final_kernel<<<24, 256>>>(part, stats, 512, 1.0f / 4194304.0f);
    // 3) S partials = scale * Q'K'^T  (split-K x4, norm fused into loads)
    gemm_qk_kernel<<<dim3(4, 4, 32), 256>>>(gq, betaq, gk, betak);
    // 4) softmax rows (fuses split-K reduction)
    softmax_kernel<<<4096, 256>>>();
    // 5) Vo = P V' (norm fused), permuted write into Z
    gemm_pv_kernel<<<dim3(64, 4, 8), 256>>>(gv, betav);
    // 6) final projection via tf32 mma.sync (+ fused norm partials)
    conv_mma_kernel<<<dim3(512, 2, 2), 256>>>(Z, Yp, Wp, Wp, Wp, bp, bp, bp, part);
    // 7) finalize per-sample stats: 2 groups x 2048 partials
    reduce_final_kernel<<<2, 256>>>(part, stats + 24, 2048, 1.0f / 16777216.0f);
    // 8) normalize + PReLU + residual
    apply_final_kernel<<<32768, 256>>>(x, gp, betap, stats + 24, (float*)d_out);
}

// round 6
// speedup vs baseline: 3.0248x; 1.9226x over previous
#include <cuda_runtime.h>
#include <cstdint>

// Problem constants: B=2, C=256, T=512, F=128, N=4 heads, H=CN=64, D=H*F=8192
#define TFsz 65536            // T*F
typedef unsigned long long u64;

// -------- scratch (device globals; no allocations allowed) --------
__device__ float g_Y3[100663296];   // [3][B][256][TF] Q,K,V (pre-norm)
__device__ float g_Sp[8388608];     // [4 kchunks][8 g][512][512] partial scores
__device__ float g_S[2097152];      // [8][512][512] attention probs
__device__ float g_Z[33554432];     // [B][256][TF] permuted attention output
__device__ float g_Yp[33554432];    // [B][256][TF] final conv output (pre-norm)
__device__ float2 g_part[12288];    // partial (sum, sumsq) from GEMM epilogues
__device__ float2 g_stats[32];      // (mu, rstd): [0..23] qkv groups, [24..25] final

// -------- tf32 helpers (portable mma.sync path; no "a"-gated features) ----
__device__ __forceinline__ uint32_t f2tf32(float v) {
    uint32_t r; asm("cvt.rna.tf32.f32 %0, %1;" : "=r"(r) : "f"(v)); return r;
}
__device__ __forceinline__ void mma_tf32(float c[4], const uint32_t a[4], const uint32_t b[2]) {
    asm volatile(
        "mma.sync.aligned.m16n8k8.row.col.f32.tf32.tf32.f32 "
        "{%0,%1,%2,%3}, {%4,%5,%6,%7}, {%8,%9}, {%0,%1,%2,%3};"
        : "+f"(c[0]), "+f"(c[1]), "+f"(c[2]), "+f"(c[3])
        : "r"(a[0]), "r"(a[1]), "r"(a[2]), "r"(a[3]), "r"(b[0]), "r"(b[1]));
}
__device__ __forceinline__ float napply(float v, float gg, float of) {
    float y = fmaf(v, gg, of);
    return (y >= 0.f) ? y : 0.25f * y;
}

// ---------------------------------------------------------------------------
// tf32 mma.sync conv GEMM: Out[tens*2+b][o][j] = bias[o] + sum_c W[o][c]*X[b][c][j]
// Block 128(o) x 128(j), K-chunks of 32; 8 warps, each 4x4 m16n8k8.
// Fragment maps (m16n8k8.row.col, lane g=l>>2, t=l&3):
//   A: a0=(g,t) a1=(g+8,t) a2=(g,t+4) a3=(g+8,t+4)
//   B: b0=(k=t,n=g) b1=(k=t+4,n=g)
//   C: c0=(g,2t) c1=(g,2t+1) c2=(g+8,2t) c3=(g+8,2t+1)
// Epilogue fuses bias + per-64-channel-group (sum,sumsq) partials.
// ---------------------------------------------------------------------------
__global__ void __launch_bounds__(256, 2) conv_mma_kernel(
    const float* __restrict__ X, float* __restrict__ Out,
    const float* __restrict__ W0, const float* __restrict__ W1, const float* __restrict__ W2,
    const float* __restrict__ b0_, const float* __restrict__ b1_, const float* __restrict__ b2_,
    float2* __restrict__ part)
{
    __shared__ __align__(16) uint32_t Ws[128][36];   // [o][k] tf32, pitch 36
    __shared__ __align__(16) uint32_t Xs[32][136];   // [k][j] tf32, pitch 136

    const int bb = blockIdx.z;
    const int y = blockIdx.y;
    const int tens = y >> 1;
    const int o0 = (y & 1) * 128;
    const int j0 = blockIdx.x * 128;
    const float* W    = (tens == 0) ? W0 : (tens == 1) ? W1 : W2;
    const float* bias = (tens == 0) ? b0_ : (tens == 1) ? b1_ : b2_;
    const float* Xb = X + (size_t)bb * (256 * (size_t)TFsz);
    float* O = Out + ((size_t)tens * 2 + bb) * (256 * (size_t)TFsz);

    const int tid = threadIdx.x;
    const int w = tid >> 5, l = tid & 31;
    const int g = l >> 2, t = l & 3;
    const int orow = w >> 2;
    const int jcol = w & 3;

    float c[4][4][4];
#pragma unroll
    for (int mt = 0; mt < 4; mt++)
#pragma unroll
        for (int nt = 0; nt < 4; nt++)
#pragma unroll
            for (int i = 0; i < 4; i++) c[mt][nt][i] = 0.f;

    for (int kc = 0; kc < 8; kc++) {
        float4 wv[4], xv[4];
#pragma unroll
        for (int it = 0; it < 4; it++) {
            int i4 = tid + it * 256;
            int row = i4 >> 3, col4 = i4 & 7;
            wv[it] = *reinterpret_cast<const float4*>(
                &W[(size_t)(o0 + row) * 256 + kc * 32 + col4 * 4]);
            int xr = i4 >> 5, xc4 = i4 & 31;
            xv[it] = *reinterpret_cast<const float4*>(
                &Xb[(size_t)(kc * 32 + xr) * TFsz + j0 + xc4 * 4]);
        }
        __syncthreads();
#pragma unroll
        for (int it = 0; it < 4; it++) {
            int i4 = tid + it * 256;
            int row = i4 >> 3, col4 = i4 & 7;
            Ws[row][col4 * 4 + 0] = f2tf32(wv[it].x);
            Ws[row][col4 * 4 + 1] = f2tf32(wv[it].y);
            Ws[row][col4 * 4 + 2] = f2tf32(wv[it].z);
            Ws[row][col4 * 4 + 3] = f2tf32(wv[it].w);
            int xr = i4 >> 5, xc4 = i4 & 31;
            uint4 u;
            u.x = f2tf32(xv[it].x); u.y = f2tf32(xv[it].y);
            u.z = f2tf32(xv[it].z); u.w = f2tf32(xv[it].w);
            *reinterpret_cast<uint4*>(&Xs[xr][xc4 * 4]) = u;
        }
        __syncthreads();

#pragma unroll
        for (int ks = 0; ks < 4; ks++) {
            const int kk = ks * 8;
            uint32_t a[4][4], b[4][2];
#pragma unroll
            for (int mt = 0; mt < 4; mt++) {
                int ow = orow * 64 + mt * 16 + g;
                a[mt][0] = Ws[ow][kk + t];
                a[mt][1] = Ws[ow + 8][kk + t];
                a[mt][2] = Ws[ow][kk + t + 4];
                a[mt][3] = Ws[ow + 8][kk + t + 4];
            }
#pragma unroll
            for (int nt = 0; nt < 4; nt++) {
                int jw = jcol * 32 + nt * 8 + g;
                b[nt][0] = Xs[kk + t][jw];
                b[nt][1] = Xs[kk + t + 4][jw];
            }
#pragma unroll
            for (int mt = 0; mt < 4; mt++)
#pragma unroll
                for (int nt = 0; nt < 4; nt++)
                    mma_tf32(c[mt][nt], a[mt], b[nt]);
        }
    }

    float bl[4], bh[4];
#pragma unroll
    for (int mt = 0; mt < 4; mt++) {
        bl[mt] = __ldg(&bias[o0 + orow * 64 + mt * 16 + g]);
        bh[mt] = __ldg(&bias[o0 + orow * 64 + mt * 16 + g + 8]);
    }
    float s = 0.f, sq = 0.f;
#pragma unroll
    for (int mt = 0; mt < 4; mt++) {
        const int o_lo = o0 + orow * 64 + mt * 16 + g;
#pragma unroll
        for (int nt = 0; nt < 4; nt++) {
            const int jj = j0 + jcol * 32 + nt * 8 + 2 * t;
            float v0 = c[mt][nt][0] + bl[mt];
            float v1 = c[mt][nt][1] + bl[mt];
            float v2 = c[mt][nt][2] + bh[mt];
            float v3 = c[mt][nt][3] + bh[mt];
            *reinterpret_cast<float2*>(&O[(size_t)o_lo * TFsz + jj]) = make_float2(v0, v1);
            *reinterpret_cast<float2*>(&O[(size_t)(o_lo + 8) * TFsz + jj]) = make_float2(v2, v3);
            s  += (v0 + v1) + (v2 + v3);
            sq += (v0 * v0 + v1 * v1) + (v2 * v2 + v3 * v3);
        }
    }

    __syncthreads();
    float* redS = reinterpret_cast<float*>(&Ws[0][0]);
    float* redQ = redS + 256;
    redS[tid] = s; redQ[tid] = sq;
    __syncthreads();
    const int r = tid & 127;
    for (int off = 64; off > 0; off >>= 1) {
        if (r < off) { redS[tid] += redS[tid + off]; redQ[tid] += redQ[tid + off]; }
        __syncthreads();
    }
    if (r == 0) {
        int og = (y & 1) * 2 + (tid >> 7);
        part[(((size_t)tens * 2 + bb) * 4 + og) * 512 + blockIdx.x] =
            make_float2(redS[tid], redQ[tid]);
    }
}

// ---------------------------------------------------------------------------
// Final reduction over `count` consecutive partials per group -> (mu, rstd)
// ---------------------------------------------------------------------------
__global__ void __launch_bounds__(256) reduce_final_kernel(
    const float2* __restrict__ part, float2* __restrict__ stats, int count, float inv_n)
{
    const int g = blockIdx.x;
    float s = 0.f, s2 = 0.f;
    for (int i = threadIdx.x; i < count; i += 256) {
        float2 v = part[(size_t)g * count + i];
        s += v.x; s2 += v.y;
    }
    __shared__ float sh[256], sh2[256];
    int t = threadIdx.x;
    sh[t] = s; sh2[t] = s2;
    __syncthreads();
    for (int off = 128; off > 0; off >>= 1) {
        if (t < off) { sh[t] += sh[t + off]; sh2[t] += sh2[t + off]; }
        __syncthreads();
    }
    if (t == 0) {
        float mu = sh[0] * inv_n;
        float var = fmaxf(sh2[0] * inv_n - mu * mu, 0.f);
        stats[g] = make_float2(mu, rsqrtf(var + 1e-6f));
    }
}

// ---------------------------------------------------------------------------
// QK via tf32 mma.sync (NT, split-K x4): Sp[c][g][t][s] = scale*sum Q'(t,k)K'(s,k)
// Block 128(t) x 128(s), k-chunks of 32 over the 2048-wide split chunk.
// Both tiles "Ws-style" [row][k] pitch 36: A frag as conv; B frag reads
// Ks[s][k] at banks 4g+t (conflict-free). Norm+PReLU fused into tile loads.
// grid (4 s-tiles, 4 t-tiles, 32 = g*4+c), 256 threads.
// ---------------------------------------------------------------------------
__global__ void __launch_bounds__(256, 2) qk_mma_kernel(
    const float* __restrict__ gq, const float* __restrict__ betaq,
    const float* __restrict__ gk, const float* __restrict__ betak)
{
    __shared__ __align__(16) uint32_t Qs[128][36];
    __shared__ __align__(16) uint32_t Ks[128][36];
    __shared__ float sgg[2][64], sof[2][64];

    const int z = blockIdx.z;
    const int g = z >> 2, c = z & 3;
    const int n = g & 3;
    const float* Q  = g_Y3 + (size_t)g * 4194304;
    const float* Km = g_Y3 + 8ull * 4194304 + (size_t)g * 4194304;
    const int t0 = blockIdx.y * 128, s0 = blockIdx.x * 128;
    const int tid = threadIdx.x;
    const int w = tid >> 5, l = tid & 31;
    const int fg = l >> 2, ft = l & 3;
    const int orow = w >> 2, jcol = w & 3;

    if (tid < 128) {
        int which = tid >> 6, h = tid & 63, o = n * 64 + h;
        float2 st = g_stats[which * 8 + g];
        const float* gw = which ? gk : gq;
        const float* bw = which ? betak : betaq;
        float gg = gw[o] * st.y;
        sgg[which][h] = gg;
        sof[which][h] = bw[o] - st.x * gg;
    }
    __syncthreads();

    float acc[4][4][4];
#pragma unroll
    for (int mt = 0; mt < 4; mt++)
#pragma unroll
        for (int nt = 0; nt < 4; nt++)
#pragma unroll
            for (int i = 0; i < 4; i++) acc[mt][nt][i] = 0.f;

    for (int kc = 0; kc < 64; kc++) {
        const int k0 = c * 2048 + kc * 32;
        const int h = k0 >> 7;
        const size_t hb = (size_t)h * 65536 + (size_t)(k0 & 127);
        const float ggq = sgg[0][h], ofq = sof[0][h];
        const float ggk = sgg[1][h], ofk = sof[1][h];
        float4 qv[4], kv[4];
#pragma unroll
        for (int it = 0; it < 4; it++) {
            int i4 = tid + it * 256;
            int r = i4 >> 3, c4 = i4 & 7;
            qv[it] = *reinterpret_cast<const float4*>(&Q[hb + (size_t)(t0 + r) * 128 + c4 * 4]);
            kv[it] = *reinterpret_cast<const float4*>(&Km[hb + (size_t)(s0 + r) * 128 + c4 * 4]);
        }
        __syncthreads();
#pragma unroll
        for (int it = 0; it < 4; it++) {
            int i4 = tid + it * 256;
            int r = i4 >> 3, c4 = i4 & 7;
            uint4 uq, uk;
            uq.x = f2tf32(napply(qv[it].x, ggq, ofq));
            uq.y = f2tf32(napply(qv[it].y, ggq, ofq));
            uq.z = f2tf32(napply(qv[it].z, ggq, ofq));
            uq.w = f2tf32(napply(qv[it].w, ggq, ofq));
            *reinterpret_cast<uint4*>(&Qs[r][c4 * 4]) = uq;
            uk.x = f2tf32(napply(kv[it].x, ggk, ofk));
            uk.y = f2tf32(napply(kv[it].y, ggk, ofk));
            uk.z = f2tf32(napply(kv[it].z, ggk, ofk));
            uk.w = f2tf32(napply(kv[it].w, ggk, ofk));
            *reinterpret_cast<uint4*>(&Ks[r][c4 * 4]) = uk;
        }
        __syncthreads();

#pragma unroll
        for (int ks = 0; ks < 4; ks++) {
            const int kk = ks * 8;
            uint32_t a[4][4], b[4][2];
#pragma unroll
            for (int mt = 0; mt < 4; mt++) {
                int tw = orow * 64 + mt * 16 + fg;
                a[mt][0] = Qs[tw][kk + ft];
                a[mt][1] = Qs[tw + 8][kk + ft];
                a[mt][2] = Qs[tw][kk + ft + 4];
                a[mt][3] = Qs[tw + 8][kk + ft + 4];
            }
#pragma unroll
            for (int nt = 0; nt < 4; nt++) {
                int sw = jcol * 32 + nt * 8 + fg;
                b[nt][0] = Ks[sw][kk + ft];
                b[nt][1] = Ks[sw][kk + ft + 4];
            }
#pragma unroll
            for (int mt = 0; mt < 4; mt++)
#pragma unroll
                for (int nt = 0; nt < 4; nt++)
                    mma_tf32(acc[mt][nt], a[mt], b[nt]);
        }
    }

    const float scale = 0.011048543456039806f;   // 1/sqrt(8192)
    float* Sg = g_Sp + (size_t)c * 2097152 + (size_t)g * 262144;
#pragma unroll
    for (int mt = 0; mt < 4; mt++) {
        const int tl = t0 + orow * 64 + mt * 16 + fg;
#pragma unroll
        for (int nt = 0; nt < 4; nt++) {
            const int sl = s0 + jcol * 32 + nt * 8 + 2 * ft;
            *reinterpret_cast<float2*>(&Sg[(size_t)tl * 512 + sl]) =
                make_float2(acc[mt][nt][0] * scale, acc[mt][nt][1] * scale);
            *reinterpret_cast<float2*>(&Sg[(size_t)(tl + 8) * 512 + sl]) =
                make_float2(acc[mt][nt][2] * scale, acc[mt][nt][3] * scale);
        }
    }
}

// ---------------------------------------------------------------------------
// Row softmax over 512, fusing the split-K partial sum. 4096 blocks.
// ---------------------------------------------------------------------------
__global__ void __launch_bounds__(256) softmax_kernel()
{
    const size_t row = (size_t)blockIdx.x * 512;
    const int t = threadIdx.x;
    float a = 0.f, b = 0.f;
#pragma unroll
    for (int c = 0; c < 4; c++) {
        const float* p = g_Sp + (size_t)c * 2097152 + row;
        a += p[t]; b += p[t + 256];
    }
    __shared__ float sh[256];
    sh[t] = fmaxf(a, b);
    __syncthreads();
    for (int off = 128; off > 0; off >>= 1) {
        if (t < off) sh[t] = fmaxf(sh[t], sh[t + off]);
        __syncthreads();
    }
    float m = sh[0];
    __syncthreads();
    float e0 = __expf(a - m), e1 = __expf(b - m);
    sh[t] = e0 + e1;
    __syncthreads();
    for (int off = 128; off > 0; off >>= 1) {
        if (t < off) sh[t] += sh[t + off];
        __syncthreads();
    }
    float inv = 1.0f / sh[0];
    float* q = g_S + row;
    q[t] = e0 * inv;
    q[t + 256] = e1 * inv;
}

// ---------------------------------------------------------------------------
// PV via tf32 mma.sync, output-transposed: M=f(128), N=t(128), K=s(512).
// Zt[f][t] = sum_s V'[s][f] * P[t][s]  ->  Z[b][n*64+cn][f*512+t]
// A = V^T from Xs-style [s][f] tile (banks 8t+g); B = P from Ws-style [t][s].
// C pairs are consecutive t -> float2 stores into the permuted layout.
// grid (64 cn, 4 t-tiles, 8 groups), 256 threads.
// ---------------------------------------------------------------------------
__global__ void __launch_bounds__(256, 2) pv_mma_kernel(
    const float* __restrict__ gv, const float* __restrict__ betav)
{
    __shared__ __align__(16) uint32_t Vs[32][136];   // [s][f] tf32
    __shared__ __align__(16) uint32_t Ps[128][36];   // [t][s] tf32

    const int g = blockIdx.z;
    const int n = g & 3, bb = g >> 2;
    const float* P = g_S + (size_t)g * 262144;
    const int cn = blockIdx.x;
    const float* Vb = g_Y3 + 16ull * 4194304 + (size_t)g * 4194304 + (size_t)cn * 65536;
    const int t0 = blockIdx.y * 128;
    float* Zb = g_Z + ((size_t)bb * 256 + (size_t)(n * 64 + cn)) * 65536;

    const int tid = threadIdx.x;
    const int w = tid >> 5, l = tid & 31;
    const int fg = l >> 2, ft = l & 3;
    const int orow = w >> 2, jcol = w & 3;

    float2 stv = g_stats[16 + g];
    const float ggv = gv[n * 64 + cn] * stv.y;
    const float ofv = betav[n * 64 + cn] - stv.x * ggv;

    float acc[4][4][4];
#pragma unroll
    for (int mt = 0; mt < 4; mt++)
#pragma unroll
        for (int nt = 0; nt < 4; nt++)
#pragma unroll
            for (int i = 0; i < 4; i++) acc[mt][nt][i] = 0.f;

    for (int kc = 0; kc < 16; kc++) {
        float4 vv[4], pp[4];
#pragma unroll
        for (int it = 0; it < 4; it++) {
            int i4 = tid + it * 256;
            int vr = i4 >> 5, vc4 = i4 & 31;
            vv[it] = *reinterpret_cast<const float4*>(&Vb[(size_t)(kc * 32 + vr) * 128 + vc4 * 4]);
            int pr = i4 >> 3, pc4 = i4 & 7;
            pp[it] = *reinterpret_cast<const float4*>(&P[(size_t)(t0 + pr) * 512 + kc * 32 + pc4 * 4]);
        }
        __syncthreads();
#pragma unroll
        for (int it = 0; it < 4; it++) {
            int i4 = tid + it * 256;
            int vr = i4 >> 5, vc4 = i4 & 31;
            uint4 u;
            u.x = f2tf32(napply(vv[it].x, ggv, ofv));
            u.y = f2tf32(napply(vv[it].y, ggv, ofv));
            u.z = f2tf32(napply(vv[it].z, ggv, ofv));
            u.w = f2tf32(napply(vv[it].w, ggv, ofv));
            *reinterpret_cast<uint4*>(&Vs[vr][vc4 * 4]) = u;
            int pr = i4 >> 3, pc4 = i4 & 7;
            Ps[pr][pc4 * 4 + 0] = f2tf32(pp[it].x);
            Ps[pr][pc4 * 4 + 1] = f2tf32(pp[it].y);
            Ps[pr][pc4 * 4 + 2] = f2tf32(pp[it].z);
            Ps[pr][pc4 * 4 + 3] = f2tf32(pp[it].w);
        }
        __syncthreads();

#pragma unroll
        for (int ks = 0; ks < 4; ks++) {
            const int kk = ks * 8;
            uint32_t a[4][4], b[4][2];
#pragma unroll
            for (int mt = 0; mt < 4; mt++) {
                int fw = orow * 64 + mt * 16 + fg;
                a[mt][0] = Vs[kk + ft][fw];
                a[mt][1] = Vs[kk + ft][fw + 8];
                a[mt][2] = Vs[kk + ft + 4][fw];
                a[mt][3] = Vs[kk + ft + 4][fw + 8];
            }
#pragma unroll
            for (int nt = 0; nt < 4; nt++) {
                int tw = jcol * 32 + nt * 8 + fg;
                b[nt][0] = Ps[tw][kk + ft];
                b[nt][1] = Ps[tw][kk + ft + 4];
            }
#pragma unroll
            for (int mt = 0; mt < 4; mt++)
#pragma unroll
                for (int nt = 0; nt < 4; nt++)
                    mma_tf32(acc[mt][nt], a[mt], b[nt]);
        }
    }

    // C: (m=f, n=t_local); c0/c1 consecutive t, c2/c3 at f+8
#pragma unroll
    for (int mt = 0; mt < 4; mt++) {
        const int f = orow * 64 + mt * 16 + fg;
#pragma unroll
        for (int nt = 0; nt < 4; nt++) {
            const int tt = t0 + jcol * 32 + nt * 8 + 2 * ft;
            *reinterpret_cast<float2*>(&Zb[(size_t)f * 512 + tt]) =
                make_float2(acc[mt][nt][0], acc[mt][nt][1]);
            *reinterpret_cast<float2*>(&Zb[(size_t)(f + 8) * 512 + tt]) =
                make_float2(acc[mt][nt][2], acc[mt][nt][3]);
        }
    }
}

// ---------------------------------------------------------------------------
// Final: out = PReLU(norm(Yp)*gp + betap) + x
// ---------------------------------------------------------------------------
__global__ void __launch_bounds__(256) apply_final_kernel(
    const float* __restrict__ x, const float* __restrict__ gp,
    const float* __restrict__ betap, const float2* __restrict__ stats2,
    float* __restrict__ out)
{
    size_t i = ((size_t)blockIdx.x * 256 + threadIdx.x) * 4;
    int r = (int)(i >> 16);
    int bidx = r >> 8;
    int o = r & 255;
    float2 st = stats2[bidx];
    float gg = gp[o] * st.y;
    float ofs = betap[o] - st.x * gg;
    float4 v  = *reinterpret_cast<const float4*>(&g_Yp[i]);
    float4 xr = *reinterpret_cast<const float4*>(&x[i]);
    v.x = fmaf(v.x, gg, ofs); v.x = ((v.x >= 0.f) ? v.x : 0.25f * v.x) + xr.x;
    v.y = fmaf(v.y, gg, ofs); v.y = ((v.y >= 0.f) ? v.y : 0.25f * v.y) + xr.y;
    v.z = fmaf(v.z, gg, ofs); v.z = ((v.z >= 0.f) ? v.z : 0.25f * v.z) + xr.z;
    v.w = fmaf(v.w, gg, ofs); v.w = ((v.w >= 0.f) ? v.w : 0.25f * v.w) + xr.w;
    *reinterpret_cast<float4*>(&out[i]) = v;
}

// ---------------------------------------------------------------------------
extern "C" void kernel_launch(void* const* d_in, const int* in_sizes, int n_in,
                              void* d_out, int out_size)
{
    const float* x     = (const float*)d_in[0];
    const float* Wq    = (const float*)d_in[1];
    const float* bq    = (const float*)d_in[2];
    const float* gq    = (const float*)d_in[3];
    const float* betaq = (const float*)d_in[4];
    const float* Wk    = (const float*)d_in[5];
    const float* bk    = (const float*)d_in[6];
    const float* gk    = (const float*)d_in[7];
    const float* betak = (const float*)d_in[8];
    const float* Wv    = (const float*)d_in[9];
    const float* bv    = (const float*)d_in[10];
    const float* gv    = (const float*)d_in[11];
    const float* betav = (const float*)d_in[12];
    const float* Wp    = (const float*)d_in[13];
    const float* bp    = (const float*)d_in[14];
    const float* gp    = (const float*)d_in[15];
    const float* betap = (const float*)d_in[16];

    float *Y3, *Z, *Yp;
    float2 *part, *stats;
    cudaGetSymbolAddress((void**)&Y3,   g_Y3);
    cudaGetSymbolAddress((void**)&Z,    g_Z);
    cudaGetSymbolAddress((void**)&Yp,   g_Yp);
    cudaGetSymbolAddress((void**)&part, g_part);
    cudaGetSymbolAddress((void**)&stats, g_stats);

    // 1) QKV projections via tf32 mma.sync (+ fused norm partials)
    conv_mma_kernel<<<dim3(512, 6, 2), 256>>>(x, Y3, Wq, Wk, Wv, bq, bk, bv, part);
    // 2) finalize QKV GroupNorm stats: 24 groups x 512 partials
    reduce_final_kernel<<<24, 256>>>(part, stats, 512, 1.0f / 4194304.0f);
    // 3) S partials = scale * Q'K'^T  (mma.sync, split-K x4, norm fused)
    qk_mma_kernel<<<dim3(4, 4, 32), 256>>>(gq, betaq, gk, betak);
    // 4) softmax rows (fuses split-K reduction)
    softmax_kernel<<<4096, 256>>>();
    // 5) Vo = P V' (mma.sync, norm fused), permuted write into Z
    pv_mma_kernel<<<dim3(64, 4, 8), 256>>>(gv, betav);
    // 6) final projection via tf32 mma.sync (+ fused norm partials)
    conv_mma_kernel<<<dim3(512, 2, 2), 256>>>(Z, Yp, Wp, Wp, Wp, bp, bp, bp, part);
    // 7) finalize per-sample stats: 2 groups x 2048 partials
    reduce_final_kernel<<<2, 256>>>(part, stats + 24, 2048, 1.0f / 16777216.0f);
    // 8) normalize + PReLU + residual
    apply_final_kernel<<<32768, 256>>>(x, gp, betap, stats + 24, (float*)d_out);
}